// round 17
// baseline (speedup 1.0000x reference)
#include <cuda_runtime.h>

#define C     256
#define H     128
#define W     128
#define GK2   72
#define KK    9
#define CPG   32            // C / GROUP
#define N_MAX 32
#define BN_EPS 1e-5f
#define SROWS 65            // 64 owned rows + 1 halo row in SMEM

// scratch (no allocations allowed); zero-init, restored to zero each run
__device__ float g_part[N_MAX * C * 2];      // per-(plane,half) pool partials
__device__ float g_wk[N_MAX * GK2];
__device__ unsigned g_cnt[N_MAX];            // pool-contribution counter (to 2C)
__device__ unsigned g_stcnt[N_MAX];          // stencil completion counter (to 2C)
__device__ volatile unsigned g_ready[N_MAX]; // per-sample "weights ready" flag

struct RowT { float4 v; float L, R; };

// ---------------------------------------------------------------------------
// One block = half a plane, fully fused:
//  1. load 65 rows (33KB) GMEM->SMEM once (streaming), pool-sum on the fly
//  2. publish pool partial; last block of the sample computes the 72 weights
//  3. spin (short) on sample flag
//  4. 3x3 reflect stencil straight from SMEM, stream out low+high
// x is read from DRAM exactly once (+halo); no L2 reuse dependency.
// ---------------------------------------------------------------------------
__global__ __launch_bounds__(256, 5) void fused_kernel(
    const float* __restrict__ x,
    const float* __restrict__ conv_w, const float* __restrict__ gate_w,
    const float* __restrict__ gamma,  const float* __restrict__ beta,
    const float* __restrict__ mean,   const float* __restrict__ var,
    float* __restrict__ out, long long half, int n) {
    __shared__ __align__(16) float sdata[SROWS * W];   // 33,280 B
    __shared__ float ws[8];
    __shared__ float sp[C];
    __shared__ float slf[GK2];
    __shared__ float sbn[GK2];
    __shared__ int   s_last;

    int bid   = blockIdx.x;
    int plane = bid >> 1;
    int hh    = bid & 1;
    int nid   = plane / C;
    int ch    = plane - nid * C;
    int g     = ch / CPG;
    int base  = hh * 64;            // first owned row
    int A     = hh ? 63 : 0;        // first row held in SMEM
    int tid   = threadIdx.x, warp = tid >> 5, lane = tid & 31;

    // ---- 1. load rows [A, A+65) into SMEM, pool-sum owned rows ----
    const float4* in4 = (const float4*)(x + (size_t)plane * (H * W)) + A * (W / 4);
    float4* s4 = (float4*)sdata;
    float sum = 0.f;
#pragma unroll
    for (int k = 0; k < 9; ++k) {
        int i = tid + k * 256;
        if (i < SROWS * (W / 4)) {              // 2080 float4
            float4 v = __ldcs(&in4[i]);
            s4[i] = v;
            int r = A + (i >> 5);
            if (r >= base && r < base + 64) sum += (v.x + v.y) + (v.z + v.w);
        }
    }
#pragma unroll
    for (int o = 16; o; o >>= 1) sum += __shfl_down_sync(0xffffffffu, sum, o);
    if (lane == 0) ws[warp] = sum;
    __syncthreads();
    if (tid == 0) {
        float t = 0.f;
#pragma unroll
        for (int i = 0; i < 8; ++i) t += ws[i];
        g_part[plane * 2 + hh] = t;
        __threadfence();
        s_last = (atomicAdd(&g_cnt[nid], 1u) == 2 * C - 1);
    }
    __syncthreads();

    // ---- 2. last block of the sample: weights (MLP+gate+BN+softmax) ----
    if (s_last) {
        __threadfence();
        sp[tid] = (__ldcg(&g_part[(nid * C + tid) * 2]) +
                   __ldcg(&g_part[(nid * C + tid) * 2 + 1])) * (1.0f / (H * W));
        __syncthreads();
#pragma unroll
        for (int o = 0; o < KK; ++o) {
            int tt = warp * KK + o;
            const float4* cw4 = (const float4*)(conv_w + tt * C);
            float4 a = cw4[lane * 2], b = cw4[lane * 2 + 1];
            int k0 = lane * 8;
            float acc = a.x * sp[k0] + a.y * sp[k0 + 1] + a.z * sp[k0 + 2] + a.w * sp[k0 + 3]
                      + b.x * sp[k0 + 4] + b.y * sp[k0 + 5] + b.z * sp[k0 + 6] + b.w * sp[k0 + 7];
#pragma unroll
            for (int off = 16; off; off >>= 1) acc += __shfl_down_sync(0xffffffffu, acc, off);
            if (lane == 0) slf[tt] = acc;
        }
        __syncthreads();
        if (tid < GK2) {
            const float* gr = gate_w + tid * GK2;
            float acc = 0.f;
#pragma unroll 8
            for (int k = 0; k < GK2; ++k) acc = fmaf(slf[k], gr[k], acc);
            float v = slf[tid];
            float gated = v * (1.0f / (1.0f + expf(-acc)));
            sbn[tid] = (gated - mean[tid]) * (gamma[tid] * rsqrtf(var[tid] + BN_EPS)) + beta[tid];
        }
        __syncthreads();
        if (tid < GK2) {
            int gg = tid / KK;
            float mx = -1e30f;
#pragma unroll
            for (int k = 0; k < KK; ++k) mx = fmaxf(mx, sbn[gg * KK + k]);
            float ssum = 0.f;
#pragma unroll
            for (int k = 0; k < KK; ++k) ssum += expf(sbn[gg * KK + k] - mx);
            g_wk[nid * GK2 + tid] = expf(sbn[tid] - mx) / ssum;
        }
        __syncthreads();
        if (tid == 0) {
            g_cnt[nid] = 0;          // reset for next graph replay
            __threadfence();
            g_ready[nid] = 1u;       // publish
        }
    }

    // ---- 3. wait for this sample's weights (short; producers co-resident) ----
    if (tid == 0) {
        while (g_ready[nid] == 0u) __nanosleep(64);
        __threadfence();
    }
    __syncthreads();

    const float* wp = &g_wk[nid * GK2 + g * KK];
    float w0 = __ldcg(wp + 0), w1 = __ldcg(wp + 1), w2 = __ldcg(wp + 2);
    float w3 = __ldcg(wp + 3), w4 = __ldcg(wp + 4), w5 = __ldcg(wp + 5);
    float w6 = __ldcg(wp + 6), w7 = __ldcg(wp + 7), w8 = __ldcg(wp + 8);

    // ---- 4. stencil from SMEM; warp w owns rows [base+8w, base+8w+8) ----
    float4* lo4 = (float4*)out + (size_t)plane * (H * W / 4);
    float4* hi4 = (float4*)(out + half) + (size_t)plane * (H * W / 4);

    auto mkS = [&](int rr) {           // rr = valid global row in [A, A+65)
        float4 v = s4[(rr - A) * (W / 4) + lane];
        RowT t; t.v = v;
        t.L = __shfl_up_sync(0xffffffffu, v.w, 1);
        t.R = __shfl_down_sync(0xffffffffu, v.x, 1);
        if (lane == 0)  t.L = v.y;     // reflect col -1 -> col 1
        if (lane == 31) t.R = v.z;     // reflect col W -> col W-2
        return t;
    };

    int y0 = base + warp * 8;
    RowT pm = mkS(y0 == 0 ? 1 : y0 - 1);        // reflect row -1 -> row 1
    RowT cm = mkS(y0);
#pragma unroll
    for (int y = y0; y < y0 + 8; ++y) {
        RowT nx = mkS(y == H - 1 ? H - 2 : y + 1);   // reflect row H -> H-2
        float4 a;
        a.x = w0 * pm.L   + w1 * pm.v.x + w2 * pm.v.y
            + w3 * cm.L   + w4 * cm.v.x + w5 * cm.v.y
            + w6 * nx.L   + w7 * nx.v.x + w8 * nx.v.y;
        a.y = w0 * pm.v.x + w1 * pm.v.y + w2 * pm.v.z
            + w3 * cm.v.x + w4 * cm.v.y + w5 * cm.v.z
            + w6 * nx.v.x + w7 * nx.v.y + w8 * nx.v.z;
        a.z = w0 * pm.v.y + w1 * pm.v.z + w2 * pm.v.w
            + w3 * cm.v.y + w4 * cm.v.z + w5 * cm.v.w
            + w6 * nx.v.y + w7 * nx.v.z + w8 * nx.v.w;
        a.w = w0 * pm.v.z + w1 * pm.v.w + w2 * pm.R
            + w3 * cm.v.z + w4 * cm.v.w + w5 * cm.R
            + w6 * nx.v.z + w7 * nx.v.w + w8 * nx.R;
        int o = y * (W / 4) + lane;
        __stcs(&lo4[o], a);
        float4 hv;
        hv.x = cm.v.x - a.x;
        hv.y = cm.v.y - a.y;
        hv.z = cm.v.z - a.z;
        hv.w = cm.v.w - a.w;
        __stcs(&hi4[o], hv);
        pm = cm;
        cm = nx;
    }

    // ---- 5. last finishing block resets the sample flag (replay safety) ----
    __syncthreads();
    if (tid == 0) {
        if (atomicAdd(&g_stcnt[nid], 1u) == 2 * C - 1) {
            g_stcnt[nid] = 0;
            g_ready[nid] = 0u;
        }
    }
}

// ---------------------------------------------------------------------------
extern "C" void kernel_launch(void* const* d_in, const int* in_sizes, int n_in,
                              void* d_out, int out_size) {
    const float* x      = (const float*)d_in[0];
    const float* conv_w = (const float*)d_in[1];
    const float* gate_w = (const float*)d_in[2];
    const float* gamma  = (const float*)d_in[3];
    const float* beta   = (const float*)d_in[4];
    const float* mean   = (const float*)d_in[5];
    const float* var    = (const float*)d_in[6];
    int n = in_sizes[0] / (C * H * W);
    long long half = (long long)out_size / 2;

    fused_kernel<<<2 * n * C, 256>>>(x, conv_w, gate_w, gamma, beta, mean,
                                     var, (float*)d_out, half, n);
}